// round 1
// baseline (speedup 1.0000x reference)
#include <cuda_runtime.h>

#define BB 16
#define SS 1024
#define DD 768
#define HH 12
#define DH 64

// Scratch (device globals — no allocation allowed)
__device__ float g_Q[(size_t)BB*HH*SS*DH];
__device__ float g_K[(size_t)BB*HH*SS*DH];
__device__ float g_V[(size_t)BB*HH*SS*DH];
__device__ float g_Ctx[(size_t)BB*SS*DD];

// ---------------------------------------------------------------------------
// Kernel 1: QKV projection. grid.x = tile*3 + mat  (S/128 = 8 tiles, 3 mats)
//           grid.y = h, grid.z = b.  Block 256 threads computes 128x64 tile.
// Q/K/V stored as [B,H,S,DH].
// ---------------------------------------------------------------------------
__global__ __launch_bounds__(256) void qkv_kernel(
    const float* __restrict__ X,
    const float* __restrict__ Wq, const float* __restrict__ bq,
    const float* __restrict__ Wk, const float* __restrict__ bk,
    const float* __restrict__ Wv, const float* __restrict__ bv)
{
    const int mat  = blockIdx.x % 3;
    const int tile = blockIdx.x / 3;
    const int h = blockIdx.y, b = blockIdx.z;

    const float* W    = (mat == 0) ? Wq : (mat == 1) ? Wk : Wv;
    const float* bias = (mat == 0) ? bq : (mat == 1) ? bk : bv;
    float* Out        = (mat == 0) ? g_Q : (mat == 1) ? g_K : g_V;

    __shared__ float Xs[128][17];   // 128 rows x 16 k, pad 17
    __shared__ float Ws[16][68];    // 16 k x 64 cols, pad 68 (16B-aligned rows)

    const int tid = threadIdx.x;
    const int tx = tid & 15, ty = tid >> 4;
    const int row0 = tile * 128;

    float acc[8][4];
    #pragma unroll
    for (int i = 0; i < 8; i++)
        #pragma unroll
        for (int j = 0; j < 4; j++) acc[i][j] = 0.f;

    const float* Xb = X + ((size_t)b * SS + row0) * DD;
    const float* Wh = W + (size_t)h * DD * DH;

    for (int k0 = 0; k0 < DD; k0 += 16) {
        #pragma unroll
        for (int i = 0; i < 8; i++) {             // 2048 elems of X tile
            int idx = tid + i * 256;
            int r = idx >> 4, kk = idx & 15;
            Xs[r][kk] = Xb[(size_t)r * DD + k0 + kk];
        }
        #pragma unroll
        for (int i = 0; i < 4; i++) {             // 1024 elems of W tile
            int idx = tid + i * 256;
            int kk = idx >> 6, c = idx & 63;
            Ws[kk][c] = Wh[(size_t)(k0 + kk) * DH + c];
        }
        __syncthreads();
        #pragma unroll
        for (int kk = 0; kk < 16; kk++) {
            float bv4[4];
            *(float4*)bv4 = *(const float4*)&Ws[kk][tx * 4];
            float a[8];
            #pragma unroll
            for (int i = 0; i < 8; i++) a[i] = Xs[ty * 8 + i][kk];
            #pragma unroll
            for (int i = 0; i < 8; i++)
                #pragma unroll
                for (int j = 0; j < 4; j++)
                    acc[i][j] = fmaf(a[i], bv4[j], acc[i][j]);
        }
        __syncthreads();
    }

    float bb[4];
    *(float4*)bb = *(const float4*)&bias[h * DH + tx * 4];
    float* Ob = Out + (((size_t)b * HH + h) * SS + row0) * DH;
    #pragma unroll
    for (int i = 0; i < 8; i++) {
        int r = ty * 8 + i;
        float4 v = make_float4(acc[i][0] + bb[0], acc[i][1] + bb[1],
                               acc[i][2] + bb[2], acc[i][3] + bb[3]);
        *(float4*)&Ob[(size_t)r * DH + tx * 4] = v;
    }
}

// ---------------------------------------------------------------------------
// Kernel 2: flash attention. grid (S/64, H, B), 256 threads.
// 64 query rows per block, loops over 16 key tiles of 64. Online softmax.
// SMEM: Qs[64][64] | KPs[64][68] (K^T, then reused as P) | Vs[64][64]
// Writes context (head-concat) to g_Ctx as [B,S,D].
// ---------------------------------------------------------------------------
#define ATTN_SMEM_FLOATS (64*64 + 64*68 + 64*64)

__global__ __launch_bounds__(256) void attn_kernel()
{
    extern __shared__ float sm[];
    float* Qs  = sm;                 // stride 64
    float* KPs = sm + 64 * 64;       // stride 68
    float* Vs  = KPs + 64 * 68;      // stride 64

    const int tid = threadIdx.x;
    const int tx = tid & 15, ty = tid >> 4;
    const int q0 = blockIdx.x * 64;
    const int h = blockIdx.y, b = blockIdx.z;

    const float* Qg = g_Q + (((size_t)b * HH + h) * SS + q0) * DH;
    const float* Kg = g_K + (((size_t)b * HH + h) * SS) * DH;
    const float* Vg = g_V + (((size_t)b * HH + h) * SS) * DH;

    #pragma unroll
    for (int i = 0; i < 16; i++) {       // Q tile, layout identical
        int idx = tid + i * 256;
        Qs[idx] = Qg[idx];
    }

    float m[4], l[4], o[4][4];
    #pragma unroll
    for (int i = 0; i < 4; i++) {
        m[i] = -1e30f; l[i] = 0.f;
        #pragma unroll
        for (int j = 0; j < 4; j++) o[i][j] = 0.f;
    }

    const float scale = 0.125f;          // 1/sqrt(64)

    for (int kt = 0; kt < SS; kt += 64) {
        __syncthreads();                 // prev iter done reading KPs/Vs
        #pragma unroll
        for (int i = 0; i < 16; i++) {   // K tile, transposed: KPs[d][key]
            int idx = tid + i * 256;
            int key = idx >> 6, d = idx & 63;
            KPs[d * 68 + key] = Kg[(size_t)(kt + key) * DH + d];
        }
        #pragma unroll
        for (int i = 0; i < 16; i++) {   // V tile direct: Vs[key][d]
            int idx = tid + i * 256;
            int key = idx >> 6, d = idx & 63;
            Vs[key * 64 + d] = Vg[(size_t)(kt + key) * DH + d];
        }
        __syncthreads();

        // S = Q @ K^T (scaled)
        float s[4][4];
        #pragma unroll
        for (int i = 0; i < 4; i++)
            #pragma unroll
            for (int j = 0; j < 4; j++) s[i][j] = 0.f;
        #pragma unroll 8
        for (int d = 0; d < 64; d++) {
            float bv4[4];
            *(float4*)bv4 = *(const float4*)&KPs[d * 68 + tx * 4];
            float a[4];
            #pragma unroll
            for (int i = 0; i < 4; i++) a[i] = Qs[(ty * 4 + i) * 64 + d];
            #pragma unroll
            for (int i = 0; i < 4; i++)
                #pragma unroll
                for (int j = 0; j < 4; j++)
                    s[i][j] = fmaf(a[i], bv4[j], s[i][j]);
        }
        __syncthreads();                 // done reading K^T, may overwrite as P

        // online softmax (row groups are 16-lane halves of a warp)
        #pragma unroll
        for (int i = 0; i < 4; i++) {
            #pragma unroll
            for (int j = 0; j < 4; j++) s[i][j] *= scale;
            float mx = fmaxf(fmaxf(s[i][0], s[i][1]), fmaxf(s[i][2], s[i][3]));
            #pragma unroll
            for (int msk = 8; msk >= 1; msk >>= 1)
                mx = fmaxf(mx, __shfl_xor_sync(0xffffffffu, mx, msk));
            float mnew = fmaxf(m[i], mx);
            float alpha = __expf(m[i] - mnew);
            float rsum = 0.f;
            #pragma unroll
            for (int j = 0; j < 4; j++) {
                float p = __expf(s[i][j] - mnew);
                s[i][j] = p; rsum += p;
            }
            #pragma unroll
            for (int msk = 8; msk >= 1; msk >>= 1)
                rsum += __shfl_xor_sync(0xffffffffu, rsum, msk);
            l[i] = l[i] * alpha + rsum;
            m[i] = mnew;
            #pragma unroll
            for (int j = 0; j < 4; j++) o[i][j] *= alpha;
        }

        // stage P into SMEM (aliases the K^T buffer)
        #pragma unroll
        for (int i = 0; i < 4; i++)
            *(float4*)&KPs[(ty * 4 + i) * 68 + tx * 4] = *(float4*)s[i];
        __syncthreads();

        // O += P @ V
        #pragma unroll 8
        for (int k = 0; k < 64; k++) {
            float bv4[4];
            *(float4*)bv4 = *(const float4*)&Vs[k * 64 + tx * 4];
            float a[4];
            #pragma unroll
            for (int i = 0; i < 4; i++) a[i] = KPs[(ty * 4 + i) * 68 + k];
            #pragma unroll
            for (int i = 0; i < 4; i++)
                #pragma unroll
                for (int j = 0; j < 4; j++)
                    o[i][j] = fmaf(a[i], bv4[j], o[i][j]);
        }
    }

    // normalize and write context (head-concat layout [B,S,D])
    float* Cg = g_Ctx + ((size_t)b * SS + q0) * DD + h * DH;
    #pragma unroll
    for (int i = 0; i < 4; i++) {
        float inv = 1.0f / l[i];
        float4 v = make_float4(o[i][0] * inv, o[i][1] * inv,
                               o[i][2] * inv, o[i][3] * inv);
        *(float4*)&Cg[(size_t)(ty * 4 + i) * DD + tx * 4] = v;
    }
}

// ---------------------------------------------------------------------------
// Kernel 3: output projection. out[16384,768] = Ctx @ Wo + bo
// grid (128, 12), 128x64 tiles, 256 threads.
// ---------------------------------------------------------------------------
__global__ __launch_bounds__(256) void proj_kernel(
    const float* __restrict__ Wo, const float* __restrict__ bo,
    float* __restrict__ out)
{
    __shared__ float As[128][17];
    __shared__ float Bs[16][68];

    const int tid = threadIdx.x;
    const int tx = tid & 15, ty = tid >> 4;
    const int row0 = blockIdx.x * 128;
    const int col0 = blockIdx.y * 64;

    float acc[8][4];
    #pragma unroll
    for (int i = 0; i < 8; i++)
        #pragma unroll
        for (int j = 0; j < 4; j++) acc[i][j] = 0.f;

    const float* A = g_Ctx + (size_t)row0 * DD;

    for (int k0 = 0; k0 < DD; k0 += 16) {
        #pragma unroll
        for (int i = 0; i < 8; i++) {
            int idx = tid + i * 256;
            int r = idx >> 4, kk = idx & 15;
            As[r][kk] = A[(size_t)r * DD + k0 + kk];
        }
        #pragma unroll
        for (int i = 0; i < 4; i++) {
            int idx = tid + i * 256;
            int kk = idx >> 6, c = idx & 63;
            Bs[kk][c] = Wo[(size_t)(k0 + kk) * DD + col0 + c];
        }
        __syncthreads();
        #pragma unroll
        for (int kk = 0; kk < 16; kk++) {
            float bv4[4];
            *(float4*)bv4 = *(const float4*)&Bs[kk][tx * 4];
            float a[8];
            #pragma unroll
            for (int i = 0; i < 8; i++) a[i] = As[ty * 8 + i][kk];
            #pragma unroll
            for (int i = 0; i < 8; i++)
                #pragma unroll
                for (int j = 0; j < 4; j++)
                    acc[i][j] = fmaf(a[i], bv4[j], acc[i][j]);
        }
        __syncthreads();
    }

    float bb[4];
    *(float4*)bb = *(const float4*)&bo[col0 + tx * 4];
    #pragma unroll
    for (int i = 0; i < 8; i++) {
        int r = row0 + ty * 8 + i;
        float4 v = make_float4(acc[i][0] + bb[0], acc[i][1] + bb[1],
                               acc[i][2] + bb[2], acc[i][3] + bb[3]);
        *(float4*)&out[(size_t)r * DD + col0 + tx * 4] = v;
    }
}

// ---------------------------------------------------------------------------
extern "C" void kernel_launch(void* const* d_in, const int* in_sizes, int n_in,
                              void* d_out, int out_size)
{
    const float* X  = (const float*)d_in[0];
    const float* Wq = (const float*)d_in[1];
    const float* bq = (const float*)d_in[2];
    const float* Wk = (const float*)d_in[3];
    const float* bk = (const float*)d_in[4];
    const float* Wv = (const float*)d_in[5];
    const float* bv = (const float*)d_in[6];
    const float* Wo = (const float*)d_in[7];
    const float* bo = (const float*)d_in[8];
    float* out = (float*)d_out;

    const int attn_smem = ATTN_SMEM_FLOATS * (int)sizeof(float);  // 50176 B
    cudaFuncSetAttribute(attn_kernel,
                         cudaFuncAttributeMaxDynamicSharedMemorySize, attn_smem);

    qkv_kernel<<<dim3(24, HH, BB), 256>>>(X, Wq, bq, Wk, bk, Wv, bv);
    attn_kernel<<<dim3(SS / 64, HH, BB), 256, attn_smem>>>();
    proj_kernel<<<dim3(SS * BB / 128, DD / 64), 256>>>(Wo, bo, out);
}